// round 5
// baseline (speedup 1.0000x reference)
#include <cuda_runtime.h>
#include <math.h>

// Problem constants: N=100000, L=48, E=1600000, ED=17, H=48
#define NN 100000
#define LL 48
#define EE 1600000
#define EDD 17
#define CAP (1<<18)
#define NCAP (1<<16)
// bit-flag words: ceil(100000/32)=3125, pad to 3136 (multiple of 4 for uint4)
#define NBW 3136

__device__ float g_x[NN*LL];
__device__ float g_v[NN*LL];
__device__ float g_agg[NN*LL];
__device__ float g_wbase[EE];
__device__ __align__(16) unsigned int g_flag1b[NBW];
__device__ __align__(16) unsigned int g_flag2b[NBW];
__device__ int g_list1[CAP];
__device__ int g_list2[CAP];
__device__ int g_list3[CAP];
__device__ int g_nlist1[NCAP];
__device__ int g_nlist2[NCAP];
__device__ int g_cnt[4];    // edge-list counters (1..3)
__device__ int g_ncnt[4];   // node-list counters (1..2)

__device__ __forceinline__ float geluf(float x) {
    return 0.5f * x * (1.0f + erff(x * 0.70710678118654752f));
}
__device__ __forceinline__ float sigm(float x) {
    return 1.0f / (1.0f + expf(-x));
}
// set bit; return true if it was previously clear
__device__ __forceinline__ bool mark_bit(unsigned int* fw, int s) {
    unsigned int b = 1u << (s & 31);
    return (atomicOr(&fw[s >> 5], b) & b) == 0u;
}

// ---------------------------------------------------------------------------
// Init: clear bit arrays (seed node 0), reset counters
// ---------------------------------------------------------------------------
__global__ void k_init() {
    int i = blockIdx.x * blockDim.x + threadIdx.x;
    if (i < NBW) {
        unsigned int seed = (i == 0) ? 1u : 0u;   // bit 0 = node 0
        g_flag1b[i] = seed;
        g_flag2b[i] = seed;
    }
    if (i == 0) {
        g_cnt[1] = g_cnt[2] = g_cnt[3] = 0;
        g_nlist1[0] = 0; g_nlist2[0] = 0;
        g_ncnt[1] = 1; g_ncnt[2] = 1;
    }
}

// ---------------------------------------------------------------------------
// Scan level 3: dst==0 edges (no flag probe); mark flag2/flag1 bits for src
// ---------------------------------------------------------------------------
__global__ void k_scan3(const int* __restrict__ src, const int* __restrict__ dst, int e) {
    int lane = threadIdx.x & 31;
    long long base = (long long)(blockIdx.x * blockDim.x + threadIdx.x) * 8;
    if (__ballot_sync(0xffffffffu, base < e) == 0u) return;

    int d[8];
    #pragma unroll
    for (int t = 0; t < 8; t++) d[t] = -1;
    if (base < e) {
        if (base + 8 <= e) {
            int4 a = __ldg((const int4*)(dst + base));
            int4 b = __ldg((const int4*)(dst + base + 4));
            d[0]=a.x; d[1]=a.y; d[2]=a.z; d[3]=a.w;
            d[4]=b.x; d[5]=b.y; d[6]=b.z; d[7]=b.w;
        } else {
            #pragma unroll
            for (int t = 0; t < 8; t++) if (base + t < e) d[t] = dst[base + t];
        }
    }
    int mymask = 0;
    #pragma unroll
    for (int t = 0; t < 8; t++) if (d[t] == 0) mymask |= 1 << t;

    if (__ballot_sync(0xffffffffu, mymask != 0)) {
        #pragma unroll
        for (int t = 0; t < 8; t++) {
            bool pred = (mymask >> t) & 1;
            unsigned int m = __ballot_sync(0xffffffffu, pred);
            if (!m) continue;
            int leader = __ffs(m) - 1;
            int pos0 = 0;
            if (lane == leader) pos0 = atomicAdd(&g_cnt[3], __popc(m));
            pos0 = __shfl_sync(0xffffffffu, pos0, leader);
            if (pred) {
                int p = pos0 + __popc(m & ((1u << lane) - 1));
                int i = (int)(base + t);
                if (p < CAP) g_list3[p] = i;
                int s = src[i];
                if (mark_bit(g_flag2b, s)) {
                    int q = atomicAdd(&g_ncnt[2], 1);
                    if (q < NCAP) g_nlist2[q] = s;
                }
                if (mark_bit(g_flag1b, s)) {
                    int q = atomicAdd(&g_ncnt[1], 1);
                    if (q < NCAP) g_nlist1[q] = s;
                }
            }
        }
    }
}

// ---------------------------------------------------------------------------
// Scan levels 2 / 1: stage 12.5KB flag BITS into smem, probe via LDS.
// level==2: probe flag2 -> list2, mark flag1 + nlist1
// level==1: probe flag1 -> list1
// ---------------------------------------------------------------------------
__global__ void k_scan_smem(const int* __restrict__ src, const int* __restrict__ dst,
                            int e, int level) {
    __shared__ __align__(16) unsigned int sflag[NBW];
    {
        const uint4* gs = (const uint4*)((level == 2) ? g_flag2b : g_flag1b);
        uint4* sd = (uint4*)sflag;
        for (int i = threadIdx.x; i < NBW / 4; i += blockDim.x) sd[i] = gs[i];
    }
    __syncthreads();

    int lane = threadIdx.x & 31;
    long long base = (long long)(blockIdx.x * blockDim.x + threadIdx.x) * 8;
    if (__ballot_sync(0xffffffffu, base < e) == 0u) return;
    int* cnt  = (level == 2) ? &g_cnt[2] : &g_cnt[1];
    int* list = (level == 2) ? g_list2 : g_list1;

    int d[8];
    #pragma unroll
    for (int t = 0; t < 8; t++) d[t] = -1;
    if (base < e) {
        if (base + 8 <= e) {
            int4 a = __ldg((const int4*)(dst + base));
            int4 b = __ldg((const int4*)(dst + base + 4));
            d[0]=a.x; d[1]=a.y; d[2]=a.z; d[3]=a.w;
            d[4]=b.x; d[5]=b.y; d[6]=b.z; d[7]=b.w;
        } else {
            #pragma unroll
            for (int t = 0; t < 8; t++) if (base + t < e) d[t] = dst[base + t];
        }
    }
    int mymask = 0;
    #pragma unroll
    for (int t = 0; t < 8; t++)
        if (d[t] >= 0 && ((sflag[d[t] >> 5] >> (d[t] & 31)) & 1u)) mymask |= 1 << t;

    if (__ballot_sync(0xffffffffu, mymask != 0)) {
        #pragma unroll
        for (int t = 0; t < 8; t++) {
            bool pred = (mymask >> t) & 1;
            unsigned int m = __ballot_sync(0xffffffffu, pred);
            if (!m) continue;
            int leader = __ffs(m) - 1;
            int pos0 = 0;
            if (lane == leader) pos0 = atomicAdd(cnt, __popc(m));
            pos0 = __shfl_sync(0xffffffffu, pos0, leader);
            if (pred) {
                int p = pos0 + __popc(m & ((1u << lane) - 1));
                int i = (int)(base + t);
                if (p < CAP) list[p] = i;
                if (level == 2) {
                    int s = src[i];
                    if (mark_bit(g_flag1b, s)) {
                        int q = atomicAdd(&g_ncnt[1], 1);
                        if (q < NCAP) g_nlist1[q] = s;
                    }
                }
            }
        }
    }
}

// ---------------------------------------------------------------------------
// wbase for list1 edges + zero g_agg for nlist1 nodes
// ---------------------------------------------------------------------------
__global__ void k_wbase_zero(const float* __restrict__ ea_all,
                             const float* __restrict__ W1, const float* __restrict__ b1,
                             const float* __restrict__ W2, const float* __restrict__ b2,
                             const float* __restrict__ Wg, const float* __restrict__ bg,
                             const float* __restrict__ Ww, const float* __restrict__ bw) {
    {
        int total = min(g_ncnt[1], NCAP) * LL;
        for (int q = blockIdx.x * blockDim.x + threadIdx.x; q < total;
             q += gridDim.x * blockDim.x) {
            int u = g_nlist1[q / LL];
            g_agg[(long long)u * LL + (q % LL)] = 0.f;
        }
    }
    int lane  = threadIdx.x & 31;
    int warp  = (blockIdx.x * blockDim.x + threadIdx.x) >> 5;
    int nwarp = (gridDim.x * blockDim.x) >> 5;
    int cnt = min(g_cnt[1], CAP);
    bool lo = (lane < 16);

    for (int it = warp; it < cnt; it += nwarp) {
        int e = g_list1[it];
        const float* ea = ea_all + (long long)e * EDD;

        float a  = b1[lane];
        float a2 = lo ? b1[lane + 32] : 0.f;
        #pragma unroll
        for (int k = 0; k < EDD; k++) {
            float ev = __ldg(&ea[k]);
            a = fmaf(ev, W1[k * 48 + lane], a);
            if (lo) a2 = fmaf(ev, W1[k * 48 + lane + 32], a2);
        }
        a = geluf(a); a2 = geluf(a2);

        float c  = b2[lane];
        float c2 = lo ? b2[lane + 32] : 0.f;
        #pragma unroll
        for (int k = 0; k < 48; k++) {
            float hk = (k < 32) ? __shfl_sync(0xffffffffu, a, k)
                                : __shfl_sync(0xffffffffu, a2, k - 32);
            c = fmaf(hk, W2[k * 48 + lane], c);
            if (lo) c2 = fmaf(hk, W2[k * 48 + lane + 32], c2);
        }
        c = fmaxf(c, 0.f); c2 = fmaxf(c2, 0.f);

        float d1 = bg[lane];
        float d2 = lo ? bg[lane + 32] : 0.f;
        #pragma unroll
        for (int k = 0; k < 48; k++) {
            float hk = (k < 32) ? __shfl_sync(0xffffffffu, c, k)
                                : __shfl_sync(0xffffffffu, c2, k - 32);
            d1 = fmaf(hk, Wg[k * 48 + lane], d1);
            if (lo) d2 = fmaf(hk, Wg[k * 48 + lane + 32], d2);
        }
        d1 = geluf(d1); d2 = geluf(d2);

        float p = d1 * Ww[lane] + (lo ? d2 * Ww[lane + 32] : 0.f);
        #pragma unroll
        for (int off = 16; off; off >>= 1) p += __shfl_xor_sync(0xffffffffu, p, off);
        if (lane == 0) g_wbase[e] = p + bw[0];
    }
}

// ---------------------------------------------------------------------------
// Level-1 aggregate (x0/v0 from nodes*valid on the fly)
// ---------------------------------------------------------------------------
__global__ void k_agg1(const int* __restrict__ src, const int* __restrict__ dst,
                       const float* __restrict__ nodes, const float* __restrict__ valid) {
    int lane  = threadIdx.x & 31;
    int warp  = (blockIdx.x * blockDim.x + threadIdx.x) >> 5;
    int nwarp = (gridDim.x * blockDim.x) >> 5;
    int cnt = min(g_cnt[1], CAP);
    bool lo = (lane < 16);

    for (int it = warp; it < cnt; it += nwarp) {
        int e = g_list1[it];
        int s = __ldg(&src[e]);
        int d = __ldg(&dst[e]);
        long long sb = (long long)s * LL;

        float v0 = __ldg(&valid[sb + lane]);
        float v1 = lo ? __ldg(&valid[sb + lane + 32]) : 0.f;
        float x0 = __ldg(&nodes[sb + lane]) * v0;
        float x1 = lo ? __ldg(&nodes[sb + lane + 32]) * v1 : 0.f;

        float sv = v0 + v1;
        #pragma unroll
        for (int off = 16; off; off >>= 1) sv += __shfl_xor_sync(0xffffffffu, sv, off);
        float sg = sigm((sv * (1.0f / 48.0f)) * g_wbase[e]);

        float* ad = g_agg + (long long)d * LL;
        atomicAdd(&ad[lane], x0 * sg);
        if (lo) atomicAdd(&ad[lane + 32], x1 * sg);
    }
}

// ---------------------------------------------------------------------------
// Fused tail (ONE block): upd1 -> agg2 -> upd2 -> agg3 -> upd3 + output.
// __syncthreads() between phases orders global atomics/stores block-wide.
// ---------------------------------------------------------------------------
__device__ __forceinline__ void tail_update(int level, const float* nodes,
                                            const float* valid, float wf0, float wf1,
                                            float wf2, float b0, float* out) {
    int cnt = (level == 3) ? 1 : min(g_ncnt[level], NCAP);
    int total = cnt * LL;
    for (int q = threadIdx.x; q < total; q += blockDim.x) {
        int u = (level == 3) ? 0 : ((level == 2) ? g_nlist2[q / LL] : g_nlist1[q / LL]);
        int l = q % LL;
        long long i = (long long)u * LL + l;

        float vv = __ldg(&valid[i]);
        float orig = __ldg(&nodes[i]) * vv;
        float xo, vo;
        if (level == 1) { xo = orig; vo = vv; }
        else            { xo = g_x[i]; vo = g_v[i]; }

        float nh = g_agg[i];
        float nv = 1.0f - vo;
        float m  = sigm(nh * wf0 + xo * wf1 + nv * wf2 + b0);
        float xn = (1.0f - m) * xo + nv * m * nh;
        float vn = (l != 0 && (orig != xn || vo > 0.0f)) ? 1.0f : 0.0f;
        g_x[i] = xn;
        g_v[i] = vn;
        g_agg[i] = 0.f;
        if (level == 3) out[l] = xn;
    }
}

__device__ __forceinline__ void tail_agg(int level, const int* src, const int* dst) {
    int lane = threadIdx.x & 31;
    int warp = threadIdx.x >> 5;
    int nwarp = blockDim.x >> 5;
    bool lo = (lane < 16);
    const int* list = (level == 2) ? g_list2 : g_list3;
    int cnt = min(g_cnt[level], CAP);

    for (int it = warp; it < cnt; it += nwarp) {
        int e = list[it];
        int s = __ldg(&src[e]);
        int d = __ldg(&dst[e]);
        long long sb = (long long)s * LL;

        float v0 = g_v[sb + lane];
        float v1 = lo ? g_v[sb + lane + 32] : 0.f;
        float x0 = g_x[sb + lane];
        float x1 = lo ? g_x[sb + lane + 32] : 0.f;

        float sv = v0 + v1;
        #pragma unroll
        for (int off = 16; off; off >>= 1) sv += __shfl_xor_sync(0xffffffffu, sv, off);
        float sg = sigm((sv * (1.0f / 48.0f)) * g_wbase[e]);

        float* ad = g_agg + (long long)d * LL;
        atomicAdd(&ad[lane], x0 * sg);
        if (lo) atomicAdd(&ad[lane + 32], x1 * sg);
    }
}

__global__ void k_tail(const int* __restrict__ src, const int* __restrict__ dst,
                       const float* __restrict__ nodes, const float* __restrict__ valid,
                       const float* __restrict__ Wf, const float* __restrict__ bf,
                       float* __restrict__ out) {
    float wf0 = Wf[0], wf1 = Wf[1], wf2 = Wf[2], b0 = bf[0];

    tail_update(1, nodes, valid, wf0, wf1, wf2, b0, out);
    __syncthreads();
    tail_agg(2, src, dst);
    __syncthreads();
    tail_update(2, nodes, valid, wf0, wf1, wf2, b0, out);
    __syncthreads();
    tail_agg(3, src, dst);
    __syncthreads();
    tail_update(3, nodes, valid, wf0, wf1, wf2, b0, out);
}

extern "C" void kernel_launch(void* const* d_in, const int* in_sizes, int n_in,
                              void* d_out, int out_size) {
    const float* nodes     = (const float*)d_in[0];
    const int*   ei        = (const int*)d_in[1];
    const float* edge_attr = (const float*)d_in[2];
    const float* valid     = (const float*)d_in[3];
    const float* W1 = (const float*)d_in[6];
    const float* b1 = (const float*)d_in[7];
    const float* W2 = (const float*)d_in[8];
    const float* b2 = (const float*)d_in[9];
    const float* Wg = (const float*)d_in[10];
    const float* bg = (const float*)d_in[11];
    const float* Ww = (const float*)d_in[12];
    const float* bw = (const float*)d_in[13];
    const float* Wf = (const float*)d_in[14];
    const float* bf = (const float*)d_in[15];

    int e = in_sizes[1] / 2;
    const int* src = ei;
    const int* dst = ei + e;
    int scan_blocks = (e / 8 + 255) / 256 + 1;

    k_init<<<(NBW + 255) / 256, 256>>>();
    k_scan3<<<scan_blocks, 256>>>(src, dst, e);
    k_scan_smem<<<scan_blocks, 256>>>(src, dst, e, 2);
    k_scan_smem<<<scan_blocks, 256>>>(src, dst, e, 1);
    k_wbase_zero<<<148, 256>>>(edge_attr, W1, b1, W2, b2, Wg, bg, Ww, bw);
    k_agg1<<<148, 256>>>(src, dst, nodes, valid);
    k_tail<<<1, 1024>>>(src, dst, nodes, valid, Wf, bf, (float*)d_out);
}

// round 6
// speedup vs baseline: 1.2544x; 1.2544x over previous
#include <cuda_runtime.h>
#include <math.h>

// Problem constants: N=100000, L=48, E=1600000, ED=17, H=48
#define NN 100000
#define LL 48
#define EDD 17
#define EEMAX 1600000
#define CAP (1<<18)
#define NCAP (1<<16)
#define NBW 3136          // ceil(100000/32)=3125 padded to x4
#define GRID 148
#define TPB 1024
#define FULL 0xffffffffu

__device__ float g_x[NN*LL];
__device__ float g_v[NN*LL];
__device__ float g_agg[NN*LL];
__device__ float g_wbase[EEMAX];
__device__ __align__(16) unsigned int g_flag1b[NBW];
__device__ __align__(16) unsigned int g_flag2b[NBW];
__device__ int g_list1[CAP];
__device__ int g_list2[CAP];
__device__ int g_list3[CAP];
__device__ int g_nlist1[NCAP];
__device__ int g_nlist2[NCAP];
__device__ int g_cnt[4];
__device__ int g_ncnt[4];
__device__ int g_bar[8];

__device__ __forceinline__ float geluf(float x) {
    return 0.5f * x * (1.0f + erff(x * 0.70710678118654752f));
}
__device__ __forceinline__ float sigm(float x) {
    return 1.0f / (1.0f + expf(-x));
}
__device__ __forceinline__ bool mark_bit(unsigned int* fw, int s) {
    unsigned int b = 1u << (s & 31);
    return (atomicOr(&fw[s >> 5], b) & b) == 0u;
}

// grid-wide software barrier: all GRID blocks are resident (1 block/SM).
__device__ __forceinline__ void gbar(int idx) {
    __syncthreads();
    if (threadIdx.x == 0) {
        __threadfence();
        atomicAdd(&g_bar[idx], 1);
        while (atomicAdd(&g_bar[idx], 0) < GRID) __nanosleep(64);
        __threadfence();
    }
    __syncthreads();
}

// ---------------------------------------------------------------------------
// Reset: barriers, counters, flag bits (seed node 0)
// ---------------------------------------------------------------------------
__global__ void k_reset() {
    int i = blockIdx.x * blockDim.x + threadIdx.x;
    if (i < NBW) {
        unsigned int seed = (i == 0) ? 1u : 0u;
        g_flag1b[i] = seed;
        g_flag2b[i] = seed;
    }
    if (i == 0) {
        g_cnt[1] = g_cnt[2] = g_cnt[3] = 0;
        g_ncnt[1] = 1; g_ncnt[2] = 1;
        g_nlist1[0] = 0; g_nlist2[0] = 0;
        #pragma unroll
        for (int k = 0; k < 8; k++) g_bar[k] = 0;
    }
}

// ---------------------------------------------------------------------------
// Persistent kernel: all phases with grid barriers between
// ---------------------------------------------------------------------------
__global__ void __launch_bounds__(TPB)
k_main(const int* __restrict__ src, const int* __restrict__ dst, int e,
       const float* __restrict__ nodes, const float* __restrict__ valid,
       const float* __restrict__ ea_all,
       const float* __restrict__ W1, const float* __restrict__ b1,
       const float* __restrict__ W2, const float* __restrict__ b2,
       const float* __restrict__ Wg, const float* __restrict__ bg,
       const float* __restrict__ Ww, const float* __restrict__ bw,
       const float* __restrict__ Wf, const float* __restrict__ bf,
       float* __restrict__ out) {
    __shared__ __align__(16) unsigned int sflag[NBW];
    const int tid = threadIdx.x;
    const int lane = tid & 31;
    const int gtid = blockIdx.x * TPB + tid;
    const int gthreads = GRID * TPB;
    const long long stride8 = (long long)gthreads * 8;

    // ---------------- Phase 1: scan3 (dst==0) ----------------
    for (long long base = (long long)gtid * 8;; base += stride8) {
        if (!__ballot_sync(FULL, base < e)) break;
        int d[8];
        #pragma unroll
        for (int t = 0; t < 8; t++) d[t] = -1;
        if (base < e) {
            if (base + 8 <= e) {
                int4 a = __ldg((const int4*)(dst + base));
                int4 b = __ldg((const int4*)(dst + base + 4));
                d[0]=a.x; d[1]=a.y; d[2]=a.z; d[3]=a.w;
                d[4]=b.x; d[5]=b.y; d[6]=b.z; d[7]=b.w;
            } else {
                #pragma unroll
                for (int t = 0; t < 8; t++) if (base + t < e) d[t] = dst[base + t];
            }
        }
        int mymask = 0;
        #pragma unroll
        for (int t = 0; t < 8; t++) if (d[t] == 0) mymask |= 1 << t;
        if (__ballot_sync(FULL, mymask != 0)) {
            #pragma unroll
            for (int t = 0; t < 8; t++) {
                bool pred = (mymask >> t) & 1;
                unsigned int m = __ballot_sync(FULL, pred);
                if (!m) continue;
                int leader = __ffs(m) - 1;
                int pos0 = 0;
                if (lane == leader) pos0 = atomicAdd(&g_cnt[3], __popc(m));
                pos0 = __shfl_sync(FULL, pos0, leader);
                if (pred) {
                    int p = pos0 + __popc(m & ((1u << lane) - 1));
                    int i = (int)(base + t);
                    if (p < CAP) g_list3[p] = i;
                    int s = src[i];
                    if (mark_bit(g_flag2b, s)) {
                        int q = atomicAdd(&g_ncnt[2], 1);
                        if (q < NCAP) g_nlist2[q] = s;
                    }
                    if (mark_bit(g_flag1b, s)) {
                        int q = atomicAdd(&g_ncnt[1], 1);
                        if (q < NCAP) g_nlist1[q] = s;
                    }
                }
            }
        }
    }
    gbar(0);

    // ---------------- Phase 2: stage flag2, scan2 ----------------
    {
        const uint4* gs = (const uint4*)g_flag2b;
        uint4* sd = (uint4*)sflag;
        for (int i = tid; i < NBW / 4; i += TPB) sd[i] = gs[i];
    }
    __syncthreads();
    for (long long base = (long long)gtid * 8;; base += stride8) {
        if (!__ballot_sync(FULL, base < e)) break;
        int d[8];
        #pragma unroll
        for (int t = 0; t < 8; t++) d[t] = -1;
        if (base < e) {
            if (base + 8 <= e) {
                int4 a = __ldg((const int4*)(dst + base));
                int4 b = __ldg((const int4*)(dst + base + 4));
                d[0]=a.x; d[1]=a.y; d[2]=a.z; d[3]=a.w;
                d[4]=b.x; d[5]=b.y; d[6]=b.z; d[7]=b.w;
            } else {
                #pragma unroll
                for (int t = 0; t < 8; t++) if (base + t < e) d[t] = dst[base + t];
            }
        }
        int mymask = 0;
        #pragma unroll
        for (int t = 0; t < 8; t++)
            if (d[t] >= 0 && ((sflag[d[t] >> 5] >> (d[t] & 31)) & 1u)) mymask |= 1 << t;
        if (__ballot_sync(FULL, mymask != 0)) {
            #pragma unroll
            for (int t = 0; t < 8; t++) {
                bool pred = (mymask >> t) & 1;
                unsigned int m = __ballot_sync(FULL, pred);
                if (!m) continue;
                int leader = __ffs(m) - 1;
                int pos0 = 0;
                if (lane == leader) pos0 = atomicAdd(&g_cnt[2], __popc(m));
                pos0 = __shfl_sync(FULL, pos0, leader);
                if (pred) {
                    int p = pos0 + __popc(m & ((1u << lane) - 1));
                    int i = (int)(base + t);
                    if (p < CAP) g_list2[p] = i;
                    int s = src[i];
                    if (mark_bit(g_flag1b, s)) {
                        int q = atomicAdd(&g_ncnt[1], 1);
                        if (q < NCAP) g_nlist1[q] = s;
                    }
                }
            }
        }
    }
    gbar(1);

    // ---------------- Phase 3: stage flag1, scan1 + zero agg ----------------
    {
        const uint4* gs = (const uint4*)g_flag1b;
        uint4* sd = (uint4*)sflag;
        for (int i = tid; i < NBW / 4; i += TPB) sd[i] = gs[i];
    }
    __syncthreads();
    for (long long base = (long long)gtid * 8;; base += stride8) {
        if (!__ballot_sync(FULL, base < e)) break;
        int d[8];
        #pragma unroll
        for (int t = 0; t < 8; t++) d[t] = -1;
        if (base < e) {
            if (base + 8 <= e) {
                int4 a = __ldg((const int4*)(dst + base));
                int4 b = __ldg((const int4*)(dst + base + 4));
                d[0]=a.x; d[1]=a.y; d[2]=a.z; d[3]=a.w;
                d[4]=b.x; d[5]=b.y; d[6]=b.z; d[7]=b.w;
            } else {
                #pragma unroll
                for (int t = 0; t < 8; t++) if (base + t < e) d[t] = dst[base + t];
            }
        }
        int mymask = 0;
        #pragma unroll
        for (int t = 0; t < 8; t++)
            if (d[t] >= 0 && ((sflag[d[t] >> 5] >> (d[t] & 31)) & 1u)) mymask |= 1 << t;
        if (__ballot_sync(FULL, mymask != 0)) {
            #pragma unroll
            for (int t = 0; t < 8; t++) {
                bool pred = (mymask >> t) & 1;
                unsigned int m = __ballot_sync(FULL, pred);
                if (!m) continue;
                int leader = __ffs(m) - 1;
                int pos0 = 0;
                if (lane == leader) pos0 = atomicAdd(&g_cnt[1], __popc(m));
                pos0 = __shfl_sync(FULL, pos0, leader);
                if (pred) {
                    int p = pos0 + __popc(m & ((1u << lane) - 1));
                    if (p < CAP) g_list1[p] = (int)(base + t);
                }
            }
        }
    }
    // zero g_agg for nlist1 nodes (final after barrier 1)
    {
        int total = min(g_ncnt[1], NCAP) * LL;
        for (int q = gtid; q < total; q += gthreads) {
            int u = g_nlist1[q / LL];
            g_agg[(long long)u * LL + (q % LL)] = 0.f;
        }
    }
    gbar(2);

    // ---------------- Phase 4: fused wbase + agg1 (warp per list1 edge) ------
    {
        int gwarp = gtid >> 5;
        int nwarp = gthreads >> 5;
        int cnt = min(g_cnt[1], CAP);
        bool lo = (lane < 16);
        float bw0 = __ldg(bw);

        for (int it = gwarp; it < cnt; it += nwarp) {
            int eid = g_list1[it];
            const float* ea = ea_all + (long long)eid * EDD;

            float a  = b1[lane];
            float a2 = lo ? b1[lane + 32] : 0.f;
            #pragma unroll
            for (int k = 0; k < EDD; k++) {
                float ev = __ldg(&ea[k]);
                a = fmaf(ev, W1[k * 48 + lane], a);
                if (lo) a2 = fmaf(ev, W1[k * 48 + lane + 32], a2);
            }
            a = geluf(a); a2 = geluf(a2);

            float c  = b2[lane];
            float c2 = lo ? b2[lane + 32] : 0.f;
            #pragma unroll
            for (int k = 0; k < 48; k++) {
                float hk = (k < 32) ? __shfl_sync(FULL, a, k)
                                    : __shfl_sync(FULL, a2, k - 32);
                c = fmaf(hk, W2[k * 48 + lane], c);
                if (lo) c2 = fmaf(hk, W2[k * 48 + lane + 32], c2);
            }
            c = fmaxf(c, 0.f); c2 = fmaxf(c2, 0.f);

            float d1 = bg[lane];
            float d2 = lo ? bg[lane + 32] : 0.f;
            #pragma unroll
            for (int k = 0; k < 48; k++) {
                float hk = (k < 32) ? __shfl_sync(FULL, c, k)
                                    : __shfl_sync(FULL, c2, k - 32);
                d1 = fmaf(hk, Wg[k * 48 + lane], d1);
                if (lo) d2 = fmaf(hk, Wg[k * 48 + lane + 32], d2);
            }
            d1 = geluf(d1); d2 = geluf(d2);

            float p = d1 * Ww[lane] + (lo ? d2 * Ww[lane + 32] : 0.f);
            #pragma unroll
            for (int off = 16; off; off >>= 1) p += __shfl_xor_sync(FULL, p, off);
            float wb = p + bw0;                 // all lanes hold wb
            if (lane == 0) g_wbase[eid] = wb;   // for tail (list2/list3 subset)

            // aggregate this edge (x0/v0 on the fly)
            int s = __ldg(&src[eid]);
            int d = __ldg(&dst[eid]);
            long long sb = (long long)s * LL;
            float v0 = __ldg(&valid[sb + lane]);
            float v1 = lo ? __ldg(&valid[sb + lane + 32]) : 0.f;
            float x0 = __ldg(&nodes[sb + lane]) * v0;
            float x1 = lo ? __ldg(&nodes[sb + lane + 32]) * v1 : 0.f;

            float sv = v0 + v1;
            #pragma unroll
            for (int off = 16; off; off >>= 1) sv += __shfl_xor_sync(FULL, sv, off);
            float sg = sigm((sv * (1.0f / 48.0f)) * wb);

            float* ad = g_agg + (long long)d * LL;
            atomicAdd(&ad[lane], x0 * sg);
            if (lo) atomicAdd(&ad[lane + 32], x1 * sg);
        }
    }
    gbar(3);

    // ---------------- Phase 5: upd1 over nlist1 ----------------
    {
        float wf0 = __ldg(&Wf[0]), wf1 = __ldg(&Wf[1]), wf2 = __ldg(&Wf[2]);
        float b0 = __ldg(bf);
        int total = min(g_ncnt[1], NCAP) * LL;
        for (int q = gtid; q < total; q += gthreads) {
            int u = g_nlist1[q / LL];
            int l = q % LL;
            long long i = (long long)u * LL + l;

            float vo = __ldg(&valid[i]);
            float orig = __ldg(&nodes[i]) * vo;
            float xo = orig;
            float nh = __ldcg(&g_agg[i]);       // bypass stale L1 (atomics wrote L2)
            float nv = 1.0f - vo;
            float m  = sigm(nh * wf0 + xo * wf1 + nv * wf2 + b0);
            float xn = (1.0f - m) * xo + nv * m * nh;
            float vn = (l != 0 && (orig != xn || vo > 0.0f)) ? 1.0f : 0.0f;
            g_x[i] = xn;
            g_v[i] = vn;
            g_agg[i] = 0.f;
        }
    }
    gbar(4);

    // ---------------- Phase 6: block 0 tail (lvl 2 + lvl 3) ----------------
    if (blockIdx.x != 0) return;
    {
        float wf0 = __ldg(&Wf[0]), wf1 = __ldg(&Wf[1]), wf2 = __ldg(&Wf[2]);
        float b0 = __ldg(bf);
        bool lo = (lane < 16);
        int warp = tid >> 5;
        int nwarp = TPB >> 5;

        #pragma unroll 1
        for (int level = 2; level <= 3; level++) {
            const int* list = (level == 2) ? g_list2 : g_list3;
            int cnt = min(g_cnt[level], CAP);
            for (int it = warp; it < cnt; it += nwarp) {
                int eid = list[it];
                int s = __ldg(&src[eid]);
                int d = __ldg(&dst[eid]);
                long long sb = (long long)s * LL;

                float v0 = g_v[sb + lane];
                float v1 = lo ? g_v[sb + lane + 32] : 0.f;
                float x0 = g_x[sb + lane];
                float x1 = lo ? g_x[sb + lane + 32] : 0.f;

                float sv = v0 + v1;
                #pragma unroll
                for (int off = 16; off; off >>= 1) sv += __shfl_xor_sync(FULL, sv, off);
                float sg = sigm((sv * (1.0f / 48.0f)) * __ldcg(&g_wbase[eid]));

                float* ad = g_agg + (long long)d * LL;
                atomicAdd(&ad[lane], x0 * sg);
                if (lo) atomicAdd(&ad[lane + 32], x1 * sg);
            }
            __syncthreads();

            int ncnt = (level == 2) ? min(g_ncnt[2], NCAP) : 1;
            int total = ncnt * LL;
            for (int q = tid; q < total; q += TPB) {
                int u = (level == 2) ? g_nlist2[q / LL] : 0;
                int l = q % LL;
                long long i = (long long)u * LL + l;

                float vv = __ldg(&valid[i]);
                float orig = __ldg(&nodes[i]) * vv;
                float xo = g_x[i];
                float vo = g_v[i];
                float nh = __ldcg(&g_agg[i]);
                float nv = 1.0f - vo;
                float m  = sigm(nh * wf0 + xo * wf1 + nv * wf2 + b0);
                float xn = (1.0f - m) * xo + nv * m * nh;
                float vn = (l != 0 && (orig != xn || vo > 0.0f)) ? 1.0f : 0.0f;
                g_x[i] = xn;
                g_v[i] = vn;
                g_agg[i] = 0.f;
                if (level == 3) out[l] = xn;
            }
            __syncthreads();
        }
    }
}

extern "C" void kernel_launch(void* const* d_in, const int* in_sizes, int n_in,
                              void* d_out, int out_size) {
    const float* nodes     = (const float*)d_in[0];
    const int*   ei        = (const int*)d_in[1];
    const float* edge_attr = (const float*)d_in[2];
    const float* valid     = (const float*)d_in[3];
    const float* W1 = (const float*)d_in[6];
    const float* b1 = (const float*)d_in[7];
    const float* W2 = (const float*)d_in[8];
    const float* b2 = (const float*)d_in[9];
    const float* Wg = (const float*)d_in[10];
    const float* bg = (const float*)d_in[11];
    const float* Ww = (const float*)d_in[12];
    const float* bw = (const float*)d_in[13];
    const float* Wf = (const float*)d_in[14];
    const float* bf = (const float*)d_in[15];

    int e = in_sizes[1] / 2;
    const int* src = ei;
    const int* dst = ei + e;

    k_reset<<<(NBW + 511) / 512, 512>>>();
    k_main<<<GRID, TPB>>>(src, dst, e, nodes, valid, edge_attr,
                          W1, b1, W2, b2, Wg, bg, Ww, bw, Wf, bf,
                          (float*)d_out);
}